// round 1
// baseline (speedup 1.0000x reference)
#include <cuda_runtime.h>
#include <math.h>

// Problem constants
#define BB 2
#define LL 1024
#define EE 1024
#define HH 16
#define DD 64
#define NCH 16          // chunks per (b,h)
#define CHK 64          // chunk length
#define ST_STRIDE 8320  // per-chunk state: Sc(4096) Ss(4096) Zc(64) Zs(64)
#define ROWS (BB*LL)    // 2048

// Scratch (device globals; no allocs allowed)
__device__ float g_xn[ROWS * EE];        // 8 MB
__device__ float g_qkv[ROWS * 3 * EE];   // 24 MB
__device__ float g_attn[ROWS * EE];      // 8 MB
__device__ float g_h[ROWS * EE];         // 8 MB
__device__ float g_mid[ROWS * 4 * EE];   // 32 MB
__device__ float g_state[BB * HH * NCH * ST_STRIDE]; // ~17 MB

// ---------------------------------------------------------------------------
// RMSNorm: one block per row (E=1024), 256 threads, 1 float4 each
// ---------------------------------------------------------------------------
__global__ void rmsnorm_kernel(const float* __restrict__ x,
                               const float* __restrict__ w,
                               float* __restrict__ out) {
    int row = blockIdx.x;
    int tid = threadIdx.x;
    const float4* xr = (const float4*)(x + (size_t)row * EE);
    float4 v = xr[tid];
    float ss = v.x*v.x + v.y*v.y + v.z*v.z + v.w*v.w;
    #pragma unroll
    for (int o = 16; o; o >>= 1) ss += __shfl_xor_sync(0xffffffffu, ss, o);
    __shared__ float red[8];
    if ((tid & 31) == 0) red[tid >> 5] = ss;
    __syncthreads();
    float tot = 0.f;
    #pragma unroll
    for (int i = 0; i < 8; i++) tot += red[i];
    float scale = rsqrtf(tot * (1.0f / (float)EE) + 1e-6f);
    float4 wv = ((const float4*)w)[tid];
    float4 o;
    o.x = v.x * scale * wv.x;
    o.y = v.y * scale * wv.y;
    o.z = v.z * scale * wv.z;
    o.w = v.w * scale * wv.w;
    ((float4*)(out + (size_t)row * EE))[tid] = o;
}

// ---------------------------------------------------------------------------
// SGEMM: C[M,N] = A[M,K] @ W[K,N] + bias, optional GELU or residual add.
// 128x128 tile, BK=8, 256 threads, 8x8 per thread, float4 loads.
// epi: 0 = bias, 1 = bias+gelu(tanh), 2 = bias+residual
// ---------------------------------------------------------------------------
__global__ void __launch_bounds__(256)
sgemm_kernel(const float* __restrict__ A, const float* __restrict__ W,
             const float* __restrict__ bias, const float* __restrict__ res,
             float* __restrict__ C, int M, int N, int K, int epi) {
    __shared__ float As[8][128];
    __shared__ float Ws[8][128];

    int tid = threadIdx.x;
    int bx = blockIdx.x;   // N tile
    int by = blockIdx.y;   // M tile
    int tx = tid & 15;     // 0..15 (N dir)
    int ty = tid >> 4;     // 0..15 (M dir)

    float acc[8][8];
    #pragma unroll
    for (int i = 0; i < 8; i++)
        #pragma unroll
        for (int j = 0; j < 8; j++) acc[i][j] = 0.f;

    int arow = tid >> 1;            // 0..127
    int acol = (tid & 1) << 2;      // 0 or 4
    int wrow = tid >> 5;            // 0..7
    int wcol = (tid & 31) << 2;     // 0..124

    const float* Ag = A + (size_t)(by * 128 + arow) * K + acol;
    const float* Wg = W + (size_t)wrow * N + bx * 128 + wcol;

    for (int k0 = 0; k0 < K; k0 += 8) {
        float4 av = *(const float4*)(Ag + k0);
        float4 wv = *(const float4*)(Wg + (size_t)k0 * N);
        As[acol + 0][arow] = av.x;
        As[acol + 1][arow] = av.y;
        As[acol + 2][arow] = av.z;
        As[acol + 3][arow] = av.w;
        *(float4*)&Ws[wrow][wcol] = wv;
        __syncthreads();
        #pragma unroll
        for (int kk = 0; kk < 8; kk++) {
            float a[8], b[8];
            *(float4*)(a)     = *(const float4*)&As[kk][ty * 8];
            *(float4*)(a + 4) = *(const float4*)&As[kk][ty * 8 + 4];
            *(float4*)(b)     = *(const float4*)&Ws[kk][tx * 8];
            *(float4*)(b + 4) = *(const float4*)&Ws[kk][tx * 8 + 4];
            #pragma unroll
            for (int i = 0; i < 8; i++)
                #pragma unroll
                for (int j = 0; j < 8; j++) acc[i][j] = fmaf(a[i], b[j], acc[i][j]);
        }
        __syncthreads();
    }

    int row0 = by * 128 + ty * 8;
    int col0 = bx * 128 + tx * 8;
    float bv[8];
    #pragma unroll
    for (int j = 0; j < 8; j++) bv[j] = bias[col0 + j];

    #pragma unroll
    for (int i = 0; i < 8; i++) {
        size_t coff = (size_t)(row0 + i) * N + col0;
        float v[8];
        #pragma unroll
        for (int j = 0; j < 8; j++) {
            float t = acc[i][j] + bv[j];
            if (epi == 1) {
                // jax.nn.gelu approximate=True
                float u = t * (0.7978845608028654f + 0.035677408136300125f * t * t);
                t = 0.5f * t * (1.f + tanhf(u));
            } else if (epi == 2) {
                t += res[coff + j];
            }
            v[j] = t;
        }
        *(float4*)(C + coff)     = make_float4(v[0], v[1], v[2], v[3]);
        *(float4*)(C + coff + 4) = make_float4(v[4], v[5], v[6], v[7]);
    }
}

// ---------------------------------------------------------------------------
// Attention pass A: per-chunk state sums.
//   Sc[d][e] = sum_j kp[j][d]*cos(th_j)*v[j][e], Ss likewise with sin.
//   Zc[d]    = sum_j kp[j][d]*cos(th_j),        Zs likewise.
// grid = B*H*NCH blocks, 256 threads.
// ---------------------------------------------------------------------------
__global__ void __launch_bounds__(256)
attn_chunk_state(const float* __restrict__ qkv, float* __restrict__ state) {
    int blk = blockIdx.x;
    int c = blk % NCH;
    int bh = blk / NCH;
    int b = bh / HH, h = bh % HH;

    __shared__ float sk[CHK][DD + 1];
    __shared__ float sv[CHK][DD + 1];
    __shared__ float cw[CHK], sw[CHK];

    int tid = threadIdx.x;
    for (int idx = tid; idx < CHK * 16; idx += 256) {
        int j = idx >> 4;
        int dd = (idx & 15) << 2;
        int l = c * CHK + j;
        const float* base = qkv + (size_t)(b * LL + l) * (3 * EE) + h * DD;
        float4 kv = *(const float4*)(base + EE + dd);
        float4 vv = *(const float4*)(base + 2 * EE + dd);
        sk[j][dd + 0] = fmaxf(kv.x, 0.f);
        sk[j][dd + 1] = fmaxf(kv.y, 0.f);
        sk[j][dd + 2] = fmaxf(kv.z, 0.f);
        sk[j][dd + 3] = fmaxf(kv.w, 0.f);
        sv[j][dd + 0] = vv.x;
        sv[j][dd + 1] = vv.y;
        sv[j][dd + 2] = vv.z;
        sv[j][dd + 3] = vv.w;
    }
    if (tid < CHK) {
        float ang = 1.5707963267948966f * (float)(c * CHK + tid) / (float)LL;
        cw[tid] = cosf(ang);
        sw[tid] = sinf(ang);
    }
    __syncthreads();

    int e  = tid & 63;
    int d0 = (tid >> 6) * 16;
    float accC[16], accS[16];
    #pragma unroll
    for (int r = 0; r < 16; r++) { accC[r] = 0.f; accS[r] = 0.f; }

    for (int j = 0; j < CHK; j++) {
        float ve = sv[j][e];
        float t1 = ve * cw[j];
        float t2 = ve * sw[j];
        #pragma unroll
        for (int r = 0; r < 16; r++) {
            float kd = sk[j][d0 + r];
            accC[r] = fmaf(kd, t1, accC[r]);
            accS[r] = fmaf(kd, t2, accS[r]);
        }
    }

    float* st = state + ((size_t)bh * NCH + c) * ST_STRIDE;
    #pragma unroll
    for (int r = 0; r < 16; r++) {
        st[(d0 + r) * 64 + e]        = accC[r];
        st[4096 + (d0 + r) * 64 + e] = accS[r];
    }
    if (tid < DD) {
        float zc = 0.f, zs = 0.f;
        for (int j = 0; j < CHK; j++) {
            float kd = sk[j][tid];
            zc = fmaf(kd, cw[j], zc);
            zs = fmaf(kd, sw[j], zs);
        }
        st[8192 + tid] = zc;
        st[8256 + tid] = zs;
    }
}

// ---------------------------------------------------------------------------
// Attention pass B: exclusive prefix over chunks (in-place).
// grid = (ceil(8320/256), 32), one thread per state element per bh.
// ---------------------------------------------------------------------------
__global__ void attn_prefix(float* __restrict__ state) {
    int bh  = blockIdx.y;
    int idx = blockIdx.x * 256 + threadIdx.x;
    if (idx >= ST_STRIDE) return;
    float* p = state + (size_t)bh * NCH * ST_STRIDE + idx;
    float vals[NCH];
    #pragma unroll
    for (int cc = 0; cc < NCH; cc++) vals[cc] = p[(size_t)cc * ST_STRIDE];
    float run = 0.f;
    #pragma unroll
    for (int cc = 0; cc < NCH; cc++) {
        p[(size_t)cc * ST_STRIDE] = run;
        run += vals[cc];
    }
}

// ---------------------------------------------------------------------------
// Attention pass C: per-chunk output.
//   A[i][j] = (qp_i . kp_j) * cos(th_i - th_j) * (j<=i)    (intra-chunk)
//   out[i]  = A @ V + cw_i * (qp_i @ Sc) + sw_i * (qp_i @ Ss)
//   norm_i  = rowsum(A) + cw_i*(qp_i.Zc) + sw_i*(qp_i.Zs)
//   out /= (norm + 1e-6)
// Dynamic smem ~102 KB. grid = B*H*NCH, 256 threads.
// ---------------------------------------------------------------------------
#define ATTN_SMEM_FLOATS (6 * 64 * 65 + 64 + 64 + 64 + 64 + 256 + 64)
#define ATTN_SMEM_BYTES (ATTN_SMEM_FLOATS * 4)

__global__ void __launch_bounds__(256)
attn_out_kernel(const float* __restrict__ qkv, const float* __restrict__ state,
                float* __restrict__ out) {
    extern __shared__ float sm[];
    float* sq = sm;                 // 64*65
    float* sk = sq + 4160;          // 64*65
    float* sv = sk + 4160;          // 64*65
    float* Sc = sv + 4160;          // 64*65
    float* Ss = Sc + 4160;          // 64*65
    float* AS = Ss + 4160;          // 64*65
    float* cw = AS + 4160;          // 64
    float* sw = cw + 64;            // 64
    float* Zc = sw + 64;            // 64
    float* Zs = Zc + 64;            // 64
    float* normp = Zs + 64;         // 4*64
    float* normF = normp + 256;     // 64

    int blk = blockIdx.x;
    int c = blk % NCH;
    int bh = blk / NCH;
    int b = bh / HH, h = bh % HH;
    int tid = threadIdx.x;

    const float* st = state + ((size_t)bh * NCH + c) * ST_STRIDE;

    // loads
    for (int idx = tid; idx < CHK * 16; idx += 256) {
        int j = idx >> 4;
        int dd = (idx & 15) << 2;
        int l = c * CHK + j;
        const float* base = qkv + (size_t)(b * LL + l) * (3 * EE) + h * DD;
        float4 qv = *(const float4*)(base + dd);
        float4 kv = *(const float4*)(base + EE + dd);
        float4 vv = *(const float4*)(base + 2 * EE + dd);
        int ro = j * 65 + dd;
        sq[ro + 0] = fmaxf(qv.x, 0.f); sq[ro + 1] = fmaxf(qv.y, 0.f);
        sq[ro + 2] = fmaxf(qv.z, 0.f); sq[ro + 3] = fmaxf(qv.w, 0.f);
        sk[ro + 0] = fmaxf(kv.x, 0.f); sk[ro + 1] = fmaxf(kv.y, 0.f);
        sk[ro + 2] = fmaxf(kv.z, 0.f); sk[ro + 3] = fmaxf(kv.w, 0.f);
        sv[ro + 0] = vv.x; sv[ro + 1] = vv.y; sv[ro + 2] = vv.z; sv[ro + 3] = vv.w;
        // state tiles: flat index d*64+e
        int flat = idx << 2;
        int d = flat >> 6, e = flat & 63;
        float4 scv = *(const float4*)(st + flat);
        float4 ssv = *(const float4*)(st + 4096 + flat);
        int so = d * 65 + e;
        Sc[so + 0] = scv.x; Sc[so + 1] = scv.y; Sc[so + 2] = scv.z; Sc[so + 3] = scv.w;
        Ss[so + 0] = ssv.x; Ss[so + 1] = ssv.y; Ss[so + 2] = ssv.z; Ss[so + 3] = ssv.w;
    }
    if (tid < CHK) {
        float ang = 1.5707963267948966f * (float)(c * CHK + tid) / (float)LL;
        cw[tid] = cosf(ang);
        sw[tid] = sinf(ang);
        Zc[tid] = st[8192 + tid];
        Zs[tid] = st[8256 + tid];
    }
    __syncthreads();

    // phase 1: A = Qp Kp^T with decay weight + causal mask
    {
        int jc = tid >> 6;       // 0..3
        int i  = tid & 63;       // row
        float acc[16];
        #pragma unroll
        for (int r = 0; r < 16; r++) acc[r] = 0.f;
        for (int d = 0; d < DD; d++) {
            float qv = sq[i * 65 + d];
            #pragma unroll
            for (int r = 0; r < 16; r++)
                acc[r] = fmaf(qv, sk[(jc * 16 + r) * 65 + d], acc[r]);
        }
        float cwi = cw[i], swi = sw[i];
        float rsum = 0.f;
        #pragma unroll
        for (int r = 0; r < 16; r++) {
            int j = jc * 16 + r;
            float wgt = (j <= i) ? (cwi * cw[j] + swi * sw[j]) : 0.f;
            float a = acc[r] * wgt;
            AS[i * 65 + j] = a;
            rsum += a;
        }
        normp[jc * 64 + i] = rsum;
    }
    __syncthreads();

    // norm finalize (threads 0..63)
    if (tid < 64) {
        int i = tid;
        float n = normp[i] + normp[64 + i] + normp[128 + i] + normp[192 + i];
        float dc = 0.f, ds = 0.f;
        for (int d = 0; d < DD; d++) {
            float qv = sq[i * 65 + d];
            dc = fmaf(qv, Zc[d], dc);
            ds = fmaf(qv, Zs[d], ds);
        }
        normF[i] = n + cw[i] * dc + sw[i] * ds;
    }

    // phase 2: out = A@V + cw_i*(Qp@Sc) + sw_i*(Qp@Ss)
    int ec = tid >> 6;
    int i2 = tid & 63;
    int e0 = ec * 16;
    float accO[16], accC2[16], accS2[16];
    #pragma unroll
    for (int r = 0; r < 16; r++) { accO[r] = 0.f; accC2[r] = 0.f; accS2[r] = 0.f; }

    for (int j = 0; j < CHK; j++) {
        float av = AS[i2 * 65 + j];
        #pragma unroll
        for (int r = 0; r < 16; r++)
            accO[r] = fmaf(av, sv[j * 65 + e0 + r], accO[r]);
    }
    for (int d = 0; d < DD; d++) {
        float qv = sq[i2 * 65 + d];
        #pragma unroll
        for (int r = 0; r < 16; r++) {
            accC2[r] = fmaf(qv, Sc[d * 65 + e0 + r], accC2[r]);
            accS2[r] = fmaf(qv, Ss[d * 65 + e0 + r], accS2[r]);
        }
    }
    __syncthreads();

    float nrm = normF[i2] + 1e-6f;
    float inv = 1.0f / nrm;
    float cwi = cw[i2], swi = sw[i2];
    int lg = c * CHK + i2;
    float* op = out + (size_t)(b * LL + lg) * EE + h * DD + e0;
    #pragma unroll
    for (int r4 = 0; r4 < 4; r4++) {
        float4 o;
        o.x = (accO[r4*4+0] + cwi*accC2[r4*4+0] + swi*accS2[r4*4+0]) * inv;
        o.y = (accO[r4*4+1] + cwi*accC2[r4*4+1] + swi*accS2[r4*4+1]) * inv;
        o.z = (accO[r4*4+2] + cwi*accC2[r4*4+2] + swi*accS2[r4*4+2]) * inv;
        o.w = (accO[r4*4+3] + cwi*accC2[r4*4+3] + swi*accS2[r4*4+3]) * inv;
        *(float4*)(op + r4 * 4) = o;
    }
}

// ---------------------------------------------------------------------------
// launch
// ---------------------------------------------------------------------------
extern "C" void kernel_launch(void* const* d_in, const int* in_sizes, int n_in,
                              void* d_out, int out_size) {
    const float* x       = (const float*)d_in[0];
    const float* qkv_w   = (const float*)d_in[1];
    const float* qkv_b   = (const float*)d_in[2];
    const float* out_w   = (const float*)d_in[3];
    const float* out_b   = (const float*)d_in[4];
    const float* norm1_w = (const float*)d_in[5];
    const float* norm2_w = (const float*)d_in[6];
    const float* mlp_w1  = (const float*)d_in[7];
    const float* mlp_b1  = (const float*)d_in[8];
    const float* mlp_w2  = (const float*)d_in[9];
    const float* mlp_b2  = (const float*)d_in[10];
    float* out = (float*)d_out;

    float *xn, *qkv, *attn, *hbuf, *mid, *state;
    cudaGetSymbolAddress((void**)&xn, g_xn);
    cudaGetSymbolAddress((void**)&qkv, g_qkv);
    cudaGetSymbolAddress((void**)&attn, g_attn);
    cudaGetSymbolAddress((void**)&hbuf, g_h);
    cudaGetSymbolAddress((void**)&mid, g_mid);
    cudaGetSymbolAddress((void**)&state, g_state);

    cudaFuncSetAttribute(attn_out_kernel,
                         cudaFuncAttributeMaxDynamicSharedMemorySize,
                         ATTN_SMEM_BYTES);

    // 1. xn = rmsnorm(x, norm1_w)
    rmsnorm_kernel<<<ROWS, 256>>>(x, norm1_w, xn);
    // 2. qkv = xn @ qkv_w + qkv_b
    sgemm_kernel<<<dim3(3 * EE / 128, ROWS / 128), 256>>>(
        xn, qkv_w, qkv_b, nullptr, qkv, ROWS, 3 * EE, EE, 0);
    // 3-5. cosformer attention (chunked)
    attn_chunk_state<<<BB * HH * NCH, 256>>>(qkv, state);
    attn_prefix<<<dim3((ST_STRIDE + 255) / 256, BB * HH), 256>>>(state);
    attn_out_kernel<<<BB * HH * NCH, 256, ATTN_SMEM_BYTES>>>(qkv, state, attn);
    // 6. h = attn @ out_w + out_b + x
    sgemm_kernel<<<dim3(EE / 128, ROWS / 128), 256>>>(
        attn, out_w, out_b, x, hbuf, ROWS, EE, EE, 2);
    // 7. xn = rmsnorm(h, norm2_w)
    rmsnorm_kernel<<<ROWS, 256>>>(hbuf, norm2_w, xn);
    // 8. mid = gelu(xn @ mlp_w1 + mlp_b1)
    sgemm_kernel<<<dim3(4 * EE / 128, ROWS / 128), 256>>>(
        xn, mlp_w1, mlp_b1, nullptr, mid, ROWS, 4 * EE, EE, 1);
    // 9. out = mid @ mlp_w2 + mlp_b2 + h
    sgemm_kernel<<<dim3(EE / 128, ROWS / 128), 256>>>(
        mid, mlp_w2, mlp_b2, hbuf, out, ROWS, EE, 4 * EE, 2);
}

// round 2
// speedup vs baseline: 2.6833x; 2.6833x over previous
#include <cuda_runtime.h>
#include <math.h>
#include <stdint.h>

// Problem constants
#define BB 2
#define LL 1024
#define EE 1024
#define HH 16
#define DD 64
#define NCH 16          // chunks per (b,h)
#define CHK 64          // chunk length
#define ST_STRIDE 8320  // per-chunk state: Sc(4096) Ss(4096) Zc(64) Zs(64)
#define ROWS (BB*LL)    // 2048

// Scratch (device globals; no allocs allowed)
__device__ float g_xn[ROWS * EE];        // 8 MB
__device__ float g_qkv[ROWS * 3 * EE];   // 24 MB
__device__ float g_attn[ROWS * EE];      // 8 MB
__device__ float g_h[ROWS * EE];         // 8 MB
__device__ float g_mid[ROWS * 4 * EE];   // 32 MB
__device__ float g_state[BB * HH * NCH * ST_STRIDE]; // ~17 MB

// ---------------------------------------------------------------------------
// RMSNorm: one block per row (E=1024), 256 threads, 1 float4 each
// ---------------------------------------------------------------------------
__global__ void rmsnorm_kernel(const float* __restrict__ x,
                               const float* __restrict__ w,
                               float* __restrict__ out) {
    int row = blockIdx.x;
    int tid = threadIdx.x;
    const float4* xr = (const float4*)(x + (size_t)row * EE);
    float4 v = xr[tid];
    float ss = v.x*v.x + v.y*v.y + v.z*v.z + v.w*v.w;
    #pragma unroll
    for (int o = 16; o; o >>= 1) ss += __shfl_xor_sync(0xffffffffu, ss, o);
    __shared__ float red[8];
    if ((tid & 31) == 0) red[tid >> 5] = ss;
    __syncthreads();
    float tot = 0.f;
    #pragma unroll
    for (int i = 0; i < 8; i++) tot += red[i];
    float scale = rsqrtf(tot * (1.0f / (float)EE) + 1e-6f);
    float4 wv = ((const float4*)w)[tid];
    float4 o;
    o.x = v.x * scale * wv.x;
    o.y = v.y * scale * wv.y;
    o.z = v.z * scale * wv.z;
    o.w = v.w * scale * wv.w;
    ((float4*)(out + (size_t)row * EE))[tid] = o;
}

// ---------------------------------------------------------------------------
// TF32 tensor-core GEMM: C[M,N] = A[M,K] @ W[K,N] + bias (+GELU | +residual)
// 128x128 tile, BK=32, 256 threads = 8 warps (2 warp-rows x 4 warp-cols),
// each warp 64x32 via mma.sync.m16n8k8.tf32, fp32 accumulate.
// epi: 0 = bias, 1 = bias+gelu(tanh), 2 = bias+residual
// ---------------------------------------------------------------------------
__device__ __forceinline__ uint32_t f2tf32(float f) {
    uint32_t r;
    asm("cvt.rna.tf32.f32 %0, %1;" : "=r"(r) : "f"(f));
    return r;
}

__device__ __forceinline__ void mma_tf32(float* c, const uint32_t* a, const uint32_t* b) {
    asm volatile(
        "mma.sync.aligned.m16n8k8.row.col.f32.tf32.tf32.f32 "
        "{%0,%1,%2,%3}, {%4,%5,%6,%7}, {%8,%9}, {%0,%1,%2,%3};"
        : "+f"(c[0]), "+f"(c[1]), "+f"(c[2]), "+f"(c[3])
        : "r"(a[0]), "r"(a[1]), "r"(a[2]), "r"(a[3]),
          "r"(b[0]), "r"(b[1]));
}

__global__ void __launch_bounds__(256)
tgemm_kernel(const float* __restrict__ A, const float* __restrict__ W,
             const float* __restrict__ bias, const float* __restrict__ res,
             float* __restrict__ C, int M, int N, int K, int epi) {
    __shared__ uint32_t As[32][132];   // [k][m], tf32 bits
    __shared__ uint32_t Bs[32][132];   // [k][n], tf32 bits

    int tid = threadIdx.x;
    int bx = blockIdx.x;   // N tile
    int by = blockIdx.y;   // M tile
    int warp = tid >> 5;
    int lane = tid & 31;
    int wm = warp >> 2;    // 0..1  (M dir, 64 rows each)
    int wn = warp & 3;     // 0..3  (N dir, 32 cols each)
    int g  = lane >> 2;    // 0..7
    int tg = lane & 3;     // 0..3

    float acc[4][4][4];
    #pragma unroll
    for (int mi = 0; mi < 4; mi++)
        #pragma unroll
        for (int ni = 0; ni < 4; ni++)
            #pragma unroll
            for (int r = 0; r < 4; r++) acc[mi][ni][r] = 0.f;

    // Global load mapping
    int arow = tid >> 1;           // 0..127
    int acol = (tid & 1) * 16;     // 0 or 16 (float4 i at acol + i*4)
    const float* Ag = A + (size_t)(by * 128 + arow) * K + acol;
    int brow = tid >> 3;           // 0..31
    int bcol = (tid & 7) * 4;      // float4 i at bcol + i*32
    const float* Wg = W + (size_t)brow * N + bx * 128 + bcol;

    float4 aReg[4], bReg[4];
    #pragma unroll
    for (int i = 0; i < 4; i++) aReg[i] = *(const float4*)(Ag + i * 4);
    #pragma unroll
    for (int i = 0; i < 4; i++) bReg[i] = *(const float4*)(Wg + i * 32);

    int nT = K >> 5;
    for (int t = 0; t < nT; t++) {
        // store staged tile -> smem (convert to tf32)
        #pragma unroll
        for (int i = 0; i < 4; i++) {
            int c0 = acol + i * 4;
            As[c0 + 0][arow] = f2tf32(aReg[i].x);
            As[c0 + 1][arow] = f2tf32(aReg[i].y);
            As[c0 + 2][arow] = f2tf32(aReg[i].z);
            As[c0 + 3][arow] = f2tf32(aReg[i].w);
        }
        #pragma unroll
        for (int i = 0; i < 4; i++) {
            int n0 = bcol + i * 32;
            Bs[brow][n0 + 0] = f2tf32(bReg[i].x);
            Bs[brow][n0 + 1] = f2tf32(bReg[i].y);
            Bs[brow][n0 + 2] = f2tf32(bReg[i].z);
            Bs[brow][n0 + 3] = f2tf32(bReg[i].w);
        }
        __syncthreads();

        // stage next tile while computing
        if (t + 1 < nT) {
            const float* Ag2 = Ag + (t + 1) * 32;
            const float* Wg2 = Wg + (size_t)(t + 1) * 32 * N;
            #pragma unroll
            for (int i = 0; i < 4; i++) aReg[i] = *(const float4*)(Ag2 + i * 4);
            #pragma unroll
            for (int i = 0; i < 4; i++) bReg[i] = *(const float4*)(Wg2 + i * 32);
        }

        #pragma unroll
        for (int ks = 0; ks < 4; ks++) {
            int k0 = ks * 8;
            uint32_t af[4][4];
            #pragma unroll
            for (int mi = 0; mi < 4; mi++) {
                int m0 = wm * 64 + mi * 16;
                af[mi][0] = As[k0 + tg][m0 + g];
                af[mi][1] = As[k0 + tg][m0 + g + 8];
                af[mi][2] = As[k0 + tg + 4][m0 + g];
                af[mi][3] = As[k0 + tg + 4][m0 + g + 8];
            }
            uint32_t bf[4][2];
            #pragma unroll
            for (int ni = 0; ni < 4; ni++) {
                int n0 = wn * 32 + ni * 8;
                bf[ni][0] = Bs[k0 + tg][n0 + g];
                bf[ni][1] = Bs[k0 + tg + 4][n0 + g];
            }
            #pragma unroll
            for (int mi = 0; mi < 4; mi++)
                #pragma unroll
                for (int ni = 0; ni < 4; ni++)
                    mma_tf32(acc[mi][ni], af[mi], bf[ni]);
        }
        __syncthreads();
    }

    // Epilogue. c0:(g, 2tg) c1:(g, 2tg+1) c2:(g+8, 2tg) c3:(g+8, 2tg+1)
    #pragma unroll
    for (int mi = 0; mi < 4; mi++) {
        #pragma unroll
        for (int ni = 0; ni < 4; ni++) {
            int col = bx * 128 + wn * 32 + ni * 8 + tg * 2;
            float b0 = bias[col], b1 = bias[col + 1];
            #pragma unroll
            for (int half = 0; half < 2; half++) {
                int row = by * 128 + wm * 64 + mi * 16 + g + half * 8;
                size_t off = (size_t)row * N + col;
                float v0 = acc[mi][ni][half * 2 + 0] + b0;
                float v1 = acc[mi][ni][half * 2 + 1] + b1;
                if (epi == 1) {
                    float u0 = v0 * (0.7978845608028654f + 0.035677408136300125f * v0 * v0);
                    float u1 = v1 * (0.7978845608028654f + 0.035677408136300125f * v1 * v1);
                    v0 = 0.5f * v0 * (1.f + tanhf(u0));
                    v1 = 0.5f * v1 * (1.f + tanhf(u1));
                } else if (epi == 2) {
                    v0 += res[off];
                    v1 += res[off + 1];
                }
                *(float2*)(C + off) = make_float2(v0, v1);
            }
        }
    }
}

// ---------------------------------------------------------------------------
// Attention pass A: per-chunk state sums.
// ---------------------------------------------------------------------------
__global__ void __launch_bounds__(256)
attn_chunk_state(const float* __restrict__ qkv, float* __restrict__ state) {
    int blk = blockIdx.x;
    int c = blk % NCH;
    int bh = blk / NCH;
    int b = bh / HH, h = bh % HH;

    __shared__ float sk[CHK][DD + 1];
    __shared__ float sv[CHK][DD + 1];
    __shared__ float cw[CHK], sw[CHK];

    int tid = threadIdx.x;
    for (int idx = tid; idx < CHK * 16; idx += 256) {
        int j = idx >> 4;
        int dd = (idx & 15) << 2;
        int l = c * CHK + j;
        const float* base = qkv + (size_t)(b * LL + l) * (3 * EE) + h * DD;
        float4 kv = *(const float4*)(base + EE + dd);
        float4 vv = *(const float4*)(base + 2 * EE + dd);
        sk[j][dd + 0] = fmaxf(kv.x, 0.f);
        sk[j][dd + 1] = fmaxf(kv.y, 0.f);
        sk[j][dd + 2] = fmaxf(kv.z, 0.f);
        sk[j][dd + 3] = fmaxf(kv.w, 0.f);
        sv[j][dd + 0] = vv.x;
        sv[j][dd + 1] = vv.y;
        sv[j][dd + 2] = vv.z;
        sv[j][dd + 3] = vv.w;
    }
    if (tid < CHK) {
        float ang = 1.5707963267948966f * (float)(c * CHK + tid) / (float)LL;
        cw[tid] = cosf(ang);
        sw[tid] = sinf(ang);
    }
    __syncthreads();

    int e  = tid & 63;
    int d0 = (tid >> 6) * 16;
    float accC[16], accS[16];
    #pragma unroll
    for (int r = 0; r < 16; r++) { accC[r] = 0.f; accS[r] = 0.f; }

    for (int j = 0; j < CHK; j++) {
        float ve = sv[j][e];
        float t1 = ve * cw[j];
        float t2 = ve * sw[j];
        #pragma unroll
        for (int r = 0; r < 16; r++) {
            float kd = sk[j][d0 + r];
            accC[r] = fmaf(kd, t1, accC[r]);
            accS[r] = fmaf(kd, t2, accS[r]);
        }
    }

    float* st = state + ((size_t)bh * NCH + c) * ST_STRIDE;
    #pragma unroll
    for (int r = 0; r < 16; r++) {
        st[(d0 + r) * 64 + e]        = accC[r];
        st[4096 + (d0 + r) * 64 + e] = accS[r];
    }
    if (tid < DD) {
        float zc = 0.f, zs = 0.f;
        for (int j = 0; j < CHK; j++) {
            float kd = sk[j][tid];
            zc = fmaf(kd, cw[j], zc);
            zs = fmaf(kd, sw[j], zs);
        }
        st[8192 + tid] = zc;
        st[8256 + tid] = zs;
    }
}

// ---------------------------------------------------------------------------
// Attention pass B: exclusive prefix over chunks (in-place).
// ---------------------------------------------------------------------------
__global__ void attn_prefix(float* __restrict__ state) {
    int bh  = blockIdx.y;
    int idx = blockIdx.x * 256 + threadIdx.x;
    if (idx >= ST_STRIDE) return;
    float* p = state + (size_t)bh * NCH * ST_STRIDE + idx;
    float vals[NCH];
    #pragma unroll
    for (int cc = 0; cc < NCH; cc++) vals[cc] = p[(size_t)cc * ST_STRIDE];
    float run = 0.f;
    #pragma unroll
    for (int cc = 0; cc < NCH; cc++) {
        p[(size_t)cc * ST_STRIDE] = run;
        run += vals[cc];
    }
}

// ---------------------------------------------------------------------------
// Attention pass C: per-chunk output.
// ---------------------------------------------------------------------------
#define ATTN_SMEM_FLOATS (6 * 64 * 65 + 64 + 64 + 64 + 64 + 256 + 64)
#define ATTN_SMEM_BYTES (ATTN_SMEM_FLOATS * 4)

__global__ void __launch_bounds__(256)
attn_out_kernel(const float* __restrict__ qkv, const float* __restrict__ state,
                float* __restrict__ out) {
    extern __shared__ float sm[];
    float* sq = sm;                 // 64*65
    float* sk = sq + 4160;          // 64*65
    float* sv = sk + 4160;          // 64*65
    float* Sc = sv + 4160;          // 64*65
    float* Ss = Sc + 4160;          // 64*65
    float* AS = Ss + 4160;          // 64*65
    float* cw = AS + 4160;          // 64
    float* sw = cw + 64;            // 64
    float* Zc = sw + 64;            // 64
    float* Zs = Zc + 64;            // 64
    float* normp = Zs + 64;         // 4*64
    float* normF = normp + 256;     // 64

    int blk = blockIdx.x;
    int c = blk % NCH;
    int bh = blk / NCH;
    int b = bh / HH, h = bh % HH;
    int tid = threadIdx.x;

    const float* st = state + ((size_t)bh * NCH + c) * ST_STRIDE;

    for (int idx = tid; idx < CHK * 16; idx += 256) {
        int j = idx >> 4;
        int dd = (idx & 15) << 2;
        int l = c * CHK + j;
        const float* base = qkv + (size_t)(b * LL + l) * (3 * EE) + h * DD;
        float4 qv = *(const float4*)(base + dd);
        float4 kv = *(const float4*)(base + EE + dd);
        float4 vv = *(const float4*)(base + 2 * EE + dd);
        int ro = j * 65 + dd;
        sq[ro + 0] = fmaxf(qv.x, 0.f); sq[ro + 1] = fmaxf(qv.y, 0.f);
        sq[ro + 2] = fmaxf(qv.z, 0.f); sq[ro + 3] = fmaxf(qv.w, 0.f);
        sk[ro + 0] = fmaxf(kv.x, 0.f); sk[ro + 1] = fmaxf(kv.y, 0.f);
        sk[ro + 2] = fmaxf(kv.z, 0.f); sk[ro + 3] = fmaxf(kv.w, 0.f);
        sv[ro + 0] = vv.x; sv[ro + 1] = vv.y; sv[ro + 2] = vv.z; sv[ro + 3] = vv.w;
        int flat = idx << 2;
        int d = flat >> 6, e = flat & 63;
        float4 scv = *(const float4*)(st + flat);
        float4 ssv = *(const float4*)(st + 4096 + flat);
        int so = d * 65 + e;
        Sc[so + 0] = scv.x; Sc[so + 1] = scv.y; Sc[so + 2] = scv.z; Sc[so + 3] = scv.w;
        Ss[so + 0] = ssv.x; Ss[so + 1] = ssv.y; Ss[so + 2] = ssv.z; Ss[so + 3] = ssv.w;
    }
    if (tid < CHK) {
        float ang = 1.5707963267948966f * (float)(c * CHK + tid) / (float)LL;
        cw[tid] = cosf(ang);
        sw[tid] = sinf(ang);
        Zc[tid] = st[8192 + tid];
        Zs[tid] = st[8256 + tid];
    }
    __syncthreads();

    {
        int jc = tid >> 6;
        int i  = tid & 63;
        float acc[16];
        #pragma unroll
        for (int r = 0; r < 16; r++) acc[r] = 0.f;
        for (int d = 0; d < DD; d++) {
            float qv = sq[i * 65 + d];
            #pragma unroll
            for (int r = 0; r < 16; r++)
                acc[r] = fmaf(qv, sk[(jc * 16 + r) * 65 + d], acc[r]);
        }
        float cwi = cw[i], swi = sw[i];
        float rsum = 0.f;
        #pragma unroll
        for (int r = 0; r < 16; r++) {
            int j = jc * 16 + r;
            float wgt = (j <= i) ? (cwi * cw[j] + swi * sw[j]) : 0.f;
            float a = acc[r] * wgt;
            AS[i * 65 + j] = a;
            rsum += a;
        }
        normp[jc * 64 + i] = rsum;
    }
    __syncthreads();

    if (tid < 64) {
        int i = tid;
        float n = normp[i] + normp[64 + i] + normp[128 + i] + normp[192 + i];
        float dc = 0.f, ds = 0.f;
        for (int d = 0; d < DD; d++) {
            float qv = sq[i * 65 + d];
            dc = fmaf(qv, Zc[d], dc);
            ds = fmaf(qv, Zs[d], ds);
        }
        normF[i] = n + cw[i] * dc + sw[i] * ds;
    }

    int ec = tid >> 6;
    int i2 = tid & 63;
    int e0 = ec * 16;
    float accO[16], accC2[16], accS2[16];
    #pragma unroll
    for (int r = 0; r < 16; r++) { accO[r] = 0.f; accC2[r] = 0.f; accS2[r] = 0.f; }

    for (int j = 0; j < CHK; j++) {
        float av = AS[i2 * 65 + j];
        #pragma unroll
        for (int r = 0; r < 16; r++)
            accO[r] = fmaf(av, sv[j * 65 + e0 + r], accO[r]);
    }
    for (int d = 0; d < DD; d++) {
        float qv = sq[i2 * 65 + d];
        #pragma unroll
        for (int r = 0; r < 16; r++) {
            accC2[r] = fmaf(qv, Sc[d * 65 + e0 + r], accC2[r]);
            accS2[r] = fmaf(qv, Ss[d * 65 + e0 + r], accS2[r]);
        }
    }
    __syncthreads();

    float nrm = normF[i2] + 1e-6f;
    float inv = 1.0f / nrm;
    float cwi = cw[i2], swi = sw[i2];
    int lg = c * CHK + i2;
    float* op = out + (size_t)(b * LL + lg) * EE + h * DD + e0;
    #pragma unroll
    for (int r4 = 0; r4 < 4; r4++) {
        float4 o;
        o.x = (accO[r4*4+0] + cwi*accC2[r4*4+0] + swi*accS2[r4*4+0]) * inv;
        o.y = (accO[r4*4+1] + cwi*accC2[r4*4+1] + swi*accS2[r4*4+1]) * inv;
        o.z = (accO[r4*4+2] + cwi*accC2[r4*4+2] + swi*accS2[r4*4+2]) * inv;
        o.w = (accO[r4*4+3] + cwi*accC2[r4*4+3] + swi*accS2[r4*4+3]) * inv;
        *(float4*)(op + r4 * 4) = o;
    }
}

// ---------------------------------------------------------------------------
// launch
// ---------------------------------------------------------------------------
extern "C" void kernel_launch(void* const* d_in, const int* in_sizes, int n_in,
                              void* d_out, int out_size) {
    const float* x       = (const float*)d_in[0];
    const float* qkv_w   = (const float*)d_in[1];
    const float* qkv_b   = (const float*)d_in[2];
    const float* out_w   = (const float*)d_in[3];
    const float* out_b   = (const float*)d_in[4];
    const float* norm1_w = (const float*)d_in[5];
    const float* norm2_w = (const float*)d_in[6];
    const float* mlp_w1  = (const float*)d_in[7];
    const float* mlp_b1  = (const float*)d_in[8];
    const float* mlp_w2  = (const float*)d_in[9];
    const float* mlp_b2  = (const float*)d_in[10];
    float* out = (float*)d_out;

    float *xn, *qkv, *attn, *hbuf, *mid, *state;
    cudaGetSymbolAddress((void**)&xn, g_xn);
    cudaGetSymbolAddress((void**)&qkv, g_qkv);
    cudaGetSymbolAddress((void**)&attn, g_attn);
    cudaGetSymbolAddress((void**)&hbuf, g_h);
    cudaGetSymbolAddress((void**)&mid, g_mid);
    cudaGetSymbolAddress((void**)&state, g_state);

    cudaFuncSetAttribute(attn_out_kernel,
                         cudaFuncAttributeMaxDynamicSharedMemorySize,
                         ATTN_SMEM_BYTES);

    // 1. xn = rmsnorm(x, norm1_w)
    rmsnorm_kernel<<<ROWS, 256>>>(x, norm1_w, xn);
    // 2. qkv = xn @ qkv_w + qkv_b
    tgemm_kernel<<<dim3(3 * EE / 128, ROWS / 128), 256>>>(
        xn, qkv_w, qkv_b, nullptr, qkv, ROWS, 3 * EE, EE, 0);
    // 3-5. cosformer attention (chunked)
    attn_chunk_state<<<BB * HH * NCH, 256>>>(qkv, state);
    attn_prefix<<<dim3((ST_STRIDE + 255) / 256, BB * HH), 256>>>(state);
    attn_out_kernel<<<BB * HH * NCH, 256, ATTN_SMEM_BYTES>>>(qkv, state, attn);
    // 6. h = attn @ out_w + out_b + x
    tgemm_kernel<<<dim3(EE / 128, ROWS / 128), 256>>>(
        attn, out_w, out_b, x, hbuf, ROWS, EE, EE, 2);
    // 7. xn = rmsnorm(h, norm2_w)
    rmsnorm_kernel<<<ROWS, 256>>>(hbuf, norm2_w, xn);
    // 8. mid = gelu(xn @ mlp_w1 + mlp_b1)
    tgemm_kernel<<<dim3(4 * EE / 128, ROWS / 128), 256>>>(
        xn, mlp_w1, mlp_b1, nullptr, mid, ROWS, 4 * EE, EE, 1);
    // 9. out = mid @ mlp_w2 + mlp_b2 + h
    tgemm_kernel<<<dim3(EE / 128, ROWS / 128), 256>>>(
        mid, mlp_w2, mlp_b2, hbuf, out, ROWS, EE, 4 * EE, 2);
}